// round 11
// baseline (speedup 1.0000x reference)
#include <cuda_runtime.h>
#include <cuda_bf16.h>
#include <cstdint>
#include <math.h>

#define VOCAB 32000
#define DMODEL 256
#define NLAYER 6
#define DS 16
#define DC 4
#define DI 512
#define DTR 16
#define LSEQ 128
#define XDW 48             // DTR + 2*DS
#define NSLAB 16
#define GCTA 16
#define TT 256

// All 16 replicas are provably identical (replica-symmetric network); compute one.

// ---------------- scratch (device globals; no allocation allowed) ----------
__device__ float g_h[LSEQ*DMODEL];
__device__ float g_z[LSEQ*DI];
__device__ float g_u[LSEQ*DI];
__device__ float g_xdbl[NSLAB*LSEQ*XDW];
__device__ float g_gate[LSEQ*DI];
__device__ float g_v[LSEQ*DMODEL];
__device__ float g_hf[LSEQ*DMODEL];
__device__ unsigned g_bar[2];    // [0]=count, [1]=gen; memset to 0 each launch

// ---------------- helpers ----------
__device__ __forceinline__ float siluf(float x) { return x / (1.f + __expf(-x)); }
__device__ __forceinline__ float softplusf(float x) { return (x > 20.f) ? x : log1pf(__expf(x)); }

__device__ __forceinline__ uint32_t packbf(float x, float y) {
    __nv_bfloat162 h = __floats2bfloat162_rn(x, y);
    return *reinterpret_cast<uint32_t*>(&h);
}

__device__ __forceinline__ void mma16(float* c, const uint32_t* a, const uint32_t* b) {
    asm volatile(
        "mma.sync.aligned.m16n8k16.row.col.f32.bf16.bf16.f32 "
        "{%0,%1,%2,%3}, {%4,%5,%6,%7}, {%8,%9}, {%0,%1,%2,%3};"
        : "+f"(c[0]), "+f"(c[1]), "+f"(c[2]), "+f"(c[3])
        : "r"(a[0]), "r"(a[1]), "r"(a[2]), "r"(a[3]), "r"(b[0]), "r"(b[1]));
}

// monotonic-epoch grid barrier; g_bar zeroed before each launch.
__device__ __forceinline__ void grid_bar(unsigned* epoch) {
    __threadfence();
    __syncthreads();
    (*epoch)++;
    if (threadIdx.x == 0) {
        unsigned target = *epoch;
        if (atomicAdd(&g_bar[0], 1u) == GCTA - 1) {
            g_bar[0] = 0;
            __threadfence();
            atomicAdd(&g_bar[1], 1u);
        } else {
            while (*(volatile unsigned*)&g_bar[1] < target) { }
            __threadfence();
        }
    }
    __syncthreads();
}

#define TBN 64
#define TBK 16
#define SW 12

// ---------------- device GEMM tile (BM=128, 256 threads) ----------------
// C[0:128,N] tile at cols [n0,n0+64) = act(A @ W^T + bias)
// mode 0=store, 1=+=, 3=in_proj (n0<DI: conv+silu->uout; else z->zout)
// lnmode 1 = LayerNorm of A rows in prologue (K == LN dim).
__device__ void gemm_tile(uint32_t* sm,
          const float* A, int lda, const float* W, int ldw,
          const float* bias, float* C, int ldc,
          int M, int N, int K, int act, int mode,
          const float* lnw, const float* lnb, int lnmode,
          const float* cvw, const float* cvb,
          float* uout, float* zout, int n0) {
    constexpr int BM = 128;
    constexpr int AW = 2*BM*SW;
    constexpr int WW = 2*TBN*SW;
    uint32_t* Ash = sm;
    uint32_t* Asl = sm + AW;
    uint32_t* Wsh = sm + 2*AW;
    uint32_t* Wsl = sm + 2*AW + WW;
    float* sMean = (float*)(sm + 2*AW + 2*WW);
    float* sRstd = sMean + BM;

    int tid = threadIdx.x;
    int wid = tid >> 5, lane = tid & 31;
    int wm = wid >> 1, wn = wid & 1;
    int g = lane >> 2, t = lane & 3;

    if (lnmode) {
        for (int r = wid; r < BM; r += 8) {
            float s = 0.f, s2 = 0.f;
            for (int k = lane*4; k < K; k += 128) {
                float4 v = *reinterpret_cast<const float4*>(&A[(size_t)r*lda + k]);
                s  += v.x + v.y + v.z + v.w;
                s2 += v.x*v.x + v.y*v.y + v.z*v.z + v.w*v.w;
            }
            #pragma unroll
            for (int o = 16; o > 0; o >>= 1) {
                s  += __shfl_xor_sync(0xffffffffu, s, o);
                s2 += __shfl_xor_sync(0xffffffffu, s2, o);
            }
            if (lane == 0) {
                float mean = s / K;
                sMean[r] = mean;
                sRstd[r] = rsqrtf(s2 / K - mean*mean + 1e-5f);
            }
        }
        __syncthreads();
    }

    float acc[2][4][4] = {};
    float4 rA[2], rW;

    auto load_tile = [&](int k0) {
        #pragma unroll
        for (int i = 0; i < 2; i++) {
            int slot = tid + i*TT;
            int m = slot >> 2;
            int gk = k0 + (slot & 3)*4;
            float4 v = make_float4(0.f,0.f,0.f,0.f);
            if (m < M && gk < K) {
                v = *reinterpret_cast<const float4*>(&A[(size_t)m*lda + gk]);
                if (lnmode) {
                    float mean = sMean[m], rstd = sRstd[m];
                    float4 w4 = *reinterpret_cast<const float4*>(&lnw[gk]);
                    float4 b4 = *reinterpret_cast<const float4*>(&lnb[gk]);
                    v.x = (v.x - mean)*rstd*w4.x + b4.x;
                    v.y = (v.y - mean)*rstd*w4.y + b4.y;
                    v.z = (v.z - mean)*rstd*w4.z + b4.z;
                    v.w = (v.w - mean)*rstd*w4.w + b4.w;
                }
            }
            rA[i] = v;
        }
        {
            int gn = n0 + (tid >> 2), gk = k0 + (tid & 3)*4;
            float4 v = make_float4(0.f,0.f,0.f,0.f);
            if (gn < N && gk < K)
                v = *reinterpret_cast<const float4*>(&W[(size_t)gn*ldw + gk]);
            rW = v;
        }
    };
    auto store_tile = [&](int s) {
        #pragma unroll
        for (int i = 0; i < 2; i++) {
            int slot = tid + i*TT;
            int m = slot >> 2, kw = (slot & 3)*2;
            float4 v = rA[i];
            uint32_t h0 = packbf(v.x, v.y), h1 = packbf(v.z, v.w);
            __nv_bfloat162 b0 = *reinterpret_cast<__nv_bfloat162*>(&h0);
            __nv_bfloat162 b1 = *reinterpret_cast<__nv_bfloat162*>(&h1);
            Ash[(s*BM+m)*SW+kw]   = h0; Ash[(s*BM+m)*SW+kw+1] = h1;
            Asl[(s*BM+m)*SW+kw]   = packbf(v.x - __low2float(b0), v.y - __high2float(b0));
            Asl[(s*BM+m)*SW+kw+1] = packbf(v.z - __low2float(b1), v.w - __high2float(b1));
        }
        {
            int n = tid >> 2, kw = (tid & 3)*2;
            float4 v = rW;
            uint32_t h0 = packbf(v.x, v.y), h1 = packbf(v.z, v.w);
            __nv_bfloat162 b0 = *reinterpret_cast<__nv_bfloat162*>(&h0);
            __nv_bfloat162 b1 = *reinterpret_cast<__nv_bfloat162*>(&h1);
            Wsh[(s*TBN+n)*SW+kw]   = h0; Wsh[(s*TBN+n)*SW+kw+1] = h1;
            Wsl[(s*TBN+n)*SW+kw]   = packbf(v.x - __low2float(b0), v.y - __high2float(b0));
            Wsl[(s*TBN+n)*SW+kw+1] = packbf(v.z - __low2float(b1), v.w - __high2float(b1));
        }
    };

    int nt = (K + TBK - 1) / TBK;
    load_tile(0);
    store_tile(0);
    __syncthreads();

    for (int it = 0; it < nt; it++) {
        int cur = it & 1;
        if (it + 1 < nt) load_tile((it+1) * TBK);
        uint32_t ah[2][4], al[2][4], bh[4][2], bl[4][2];
        #pragma unroll
        for (int mf = 0; mf < 2; mf++) {
            int mr = wm*32 + mf*16;
            ah[mf][0] = Ash[(cur*BM+mr+g  )*SW+t  ];
            ah[mf][1] = Ash[(cur*BM+mr+8+g)*SW+t  ];
            ah[mf][2] = Ash[(cur*BM+mr+g  )*SW+t+4];
            ah[mf][3] = Ash[(cur*BM+mr+8+g)*SW+t+4];
            al[mf][0] = Asl[(cur*BM+mr+g  )*SW+t  ];
            al[mf][1] = Asl[(cur*BM+mr+8+g)*SW+t  ];
            al[mf][2] = Asl[(cur*BM+mr+g  )*SW+t+4];
            al[mf][3] = Asl[(cur*BM+mr+8+g)*SW+t+4];
        }
        #pragma unroll
        for (int nf = 0; nf < 4; nf++) {
            int nr = wn*32 + nf*8;
            bh[nf][0] = Wsh[(cur*TBN+nr+g)*SW+t  ];
            bh[nf][1] = Wsh[(cur*TBN+nr+g)*SW+t+4];
            bl[nf][0] = Wsl[(cur*TBN+nr+g)*SW+t  ];
            bl[nf][1] = Wsl[(cur*TBN+nr+g)*SW+t+4];
        }
        #pragma unroll
        for (int mf = 0; mf < 2; mf++)
            #pragma unroll
            for (int nf = 0; nf < 4; nf++) {
                mma16(acc[mf][nf], al[mf], bh[nf]);
                mma16(acc[mf][nf], ah[mf], bl[nf]);
                mma16(acc[mf][nf], ah[mf], bh[nf]);
            }
        if (it + 1 < nt) store_tile(cur ^ 1);
        __syncthreads();
    }

    if (mode == 3 && n0 < DI) {
        float* cb = reinterpret_cast<float*>(sm);   // [128][68]
        #pragma unroll
        for (int mf = 0; mf < 2; mf++)
            #pragma unroll
            for (int nf = 0; nf < 4; nf++)
                #pragma unroll
                for (int e = 0; e < 4; e++) {
                    int r = wm*32 + mf*16 + g + (e >> 1)*8;
                    int c = wn*32 + nf*8 + 2*t + (e & 1);
                    cb[r*68 + c] = acc[mf][nf][e];
                }
        __syncthreads();
        for (int idx = tid; idx < 128*TBN; idx += TT) {
            int tt2 = idx >> 6, c = idx & 63;
            int ch = n0 + c;
            float s = cvb[ch];
            #pragma unroll
            for (int k = 0; k < DC; k++) {
                int tp = tt2 - (DC-1) + k;
                if (tp >= 0) s += cb[tp*68 + c] * cvw[ch*DC + k];
            }
            uout[(size_t)tt2*DI + ch] = siluf(s);
        }
        __syncthreads();
        return;
    }
    #pragma unroll
    for (int mf = 0; mf < 2; mf++)
        #pragma unroll
        for (int nf = 0; nf < 4; nf++)
            #pragma unroll
            for (int e = 0; e < 4; e++) {
                int gm = wm*32 + mf*16 + g + (e >> 1)*8;
                int gn = n0 + wn*32 + nf*8 + 2*t + (e & 1);
                if (gm < M && gn < N) {
                    float v = acc[mf][nf][e];
                    if (bias) v += bias[gn];
                    if (act == 1) v = softplusf(v);
                    if (mode == 0)      C[(size_t)gm*ldc + gn] = v;
                    else if (mode == 1) C[(size_t)gm*ldc + gn] += v;
                    else                zout[(size_t)gm*DI + (gn - DI)] = v;
                }
            }
    __syncthreads();
}

// ---------------- scan phase: 32 channels per CTA, 2 recurrences/thread ---
__device__ void scan_phase(uint32_t* smw, int dchunk,
                           const float* A_log, const float* skipD,
                           const float* dpw, const float* dpb) {
    float* sdt = (float*)smw;            // [128][32], recycled as y
    float* su  = sdt + LSEQ*32;          // [128][32]
    float* sB  = su  + LSEQ*32;          // [128][16]
    float* sC  = sB  + LSEQ*16;          // [128][16]
    float* sX  = sC  + LSEQ*16;          // [128][16]
    float* sW  = sX  + LSEQ*16;          // [32][16]
    int tid = threadIdx.x;
    int base = dchunk*32;
    for (int idx = tid; idx < LSEQ*32; idx += TT) {
        int tt2 = idx >> 5, dd = idx & 31;
        su[idx] = g_u[(size_t)tt2*DI + base + dd];
    }
    for (int idx = tid; idx < LSEQ*XDW; idx += TT) {
        int tt2 = idx / XDW, c = idx - tt2*XDW;
        float v = 0.f;
        #pragma unroll
        for (int sl = 0; sl < NSLAB; sl++) v += g_xdbl[sl*LSEQ*XDW + idx];
        if (c < DTR)          sX[tt2*16 + c] = v;
        else if (c < DTR+DS)  sB[tt2*16 + c - DTR] = v;
        else                  sC[tt2*16 + c - DTR - DS] = v;
    }
    for (int idx = tid; idx < 32*DTR; idx += TT)
        sW[idx] = dpw[(base + (idx >> 4))*DTR + (idx & 15)];
    __syncthreads();
    for (int idx = tid; idx < LSEQ*32; idx += TT) {
        int tt2 = idx >> 5, dd = idx & 31;
        float a = dpb[base + dd];
        #pragma unroll
        for (int k = 0; k < DTR; k++) a += sX[tt2*16+k] * sW[dd*16+k];
        sdt[idx] = softplusf(a);
    }
    __syncthreads();
    int s = tid & 15, dl = tid >> 4;    // dl 0..15
    int d0 = base + dl, d1 = base + dl + 16;
    float Ads0 = -__expf(A_log[d0*DS + s]);
    float Ads1 = -__expf(A_log[d1*DS + s]);
    float sk0 = skipD[d0], sk1 = skipD[d1];
    float h0 = 0.f, h1 = 0.f;
    for (int tt2 = 0; tt2 < LSEQ; tt2++) {
        float Bv = sB[tt2*16+s], Cv = sC[tt2*16+s];
        float dt0 = sdt[tt2*32+dl],    u0 = su[tt2*32+dl];
        float dt1 = sdt[tt2*32+dl+16], u1 = su[tt2*32+dl+16];
        h0 = __expf(dt0*Ads0)*h0 + dt0*u0*Bv;
        h1 = __expf(dt1*Ads1)*h1 + dt1*u1*Bv;
        float p0 = h0*Cv, p1 = h1*Cv;
        #pragma unroll
        for (int m = 8; m >= 1; m >>= 1) {
            p0 += __shfl_xor_sync(0xffffffffu, p0, m, 16);
            p1 += __shfl_xor_sync(0xffffffffu, p1, m, 16);
        }
        if (s == 0) {
            sdt[tt2*32+dl]    = p0 + u0*sk0;
            sdt[tt2*32+dl+16] = p1 + u1*sk1;
        }
    }
    __syncthreads();
    for (int idx = tid; idx < LSEQ*32; idx += TT) {
        int tt2 = idx >> 5, dd = idx & 31;
        float z = g_z[(size_t)tt2*DI + base + dd];
        g_gate[(size_t)tt2*DI + base + dd] = sdt[idx] * siluf(z);
    }
    __syncthreads();
}

// ---------------- megakernel: embed + 6 layers + final LN ----------------
__global__ void __launch_bounds__(TT, 1)
k_mega(const int* __restrict__ x, const float* __restrict__ emb,
       const float* __restrict__ n1w, const float* __restrict__ n1b,
       const float* __restrict__ n2w, const float* __restrict__ n2b,
       const float* __restrict__ ipw, const float* __restrict__ cw,
       const float* __restrict__ cb,  const float* __restrict__ xpw,
       const float* __restrict__ dpw, const float* __restrict__ dpb,
       const float* __restrict__ alog,const float* __restrict__ dskip,
       const float* __restrict__ opw, const float* __restrict__ aiw,
       const float* __restrict__ aib, const float* __restrict__ aow,
       const float* __restrict__ aob, const float* __restrict__ nfw,
       const float* __restrict__ nfb) {
    extern __shared__ uint32_t dsm[];
    int cta = blockIdx.x;
    int tid = threadIdx.x;
    unsigned epoch = 0;

    // P0: embed
    for (int idx = cta*TT + tid; idx < LSEQ*DMODEL; idx += GCTA*TT)
        g_h[idx] = emb[(size_t)x[idx >> 8]*DMODEL + (idx & 255)];
    grid_bar(&epoch);

    for (int i = 0; i < NLAYER; i++) {
        const float* L_n1w = n1w + i*DMODEL;
        const float* L_n1b = n1b + i*DMODEL;
        const float* L_n2w = n2w + i*DMODEL;
        const float* L_n2b = n2b + i*DMODEL;
        const float* L_ipw = ipw + (size_t)i*2*DI*DMODEL;
        const float* L_cw  = cw  + (size_t)i*DI*DC;
        const float* L_cb  = cb  + (size_t)i*DI;
        const float* L_xpw = xpw + (size_t)i*XDW*DI;
        const float* L_dpw = dpw + (size_t)i*DI*DTR;
        const float* L_dpb = dpb + (size_t)i*DI;
        const float* L_alog= alog+ (size_t)i*DI*DS;
        const float* L_skip= dskip+(size_t)i*DI;
        const float* L_opw = opw + (size_t)i*DMODEL*DI;
        const float* L_aivw= aiw + (size_t)i*3*DMODEL*DMODEL + (size_t)2*DMODEL*DMODEL;
        const float* L_aivb= aib + (size_t)i*3*DMODEL + 2*DMODEL;
        const float* L_aow = aow + (size_t)i*DMODEL*DMODEL;
        const float* L_aob = aob + (size_t)i*DMODEL;

        // P1: in_proj (LN1 fused) + conv+silu / z
        gemm_tile(dsm, g_h, DMODEL, L_ipw, DMODEL, nullptr, nullptr, 0,
                  LSEQ, 2*DI, DMODEL, 0, 3, L_n1w, L_n1b, 1,
                  L_cw, L_cb, g_u, g_z, cta*TBN);
        grid_bar(&epoch);
        // P2: xdbl slab (split-K 16)
        gemm_tile(dsm, g_u + cta*(DI/NSLAB), DI, L_xpw + cta*(DI/NSLAB), DI,
                  nullptr, g_xdbl + (size_t)cta*LSEQ*XDW, XDW,
                  LSEQ, XDW, DI/NSLAB, 0, 0, nullptr, nullptr, 0,
                  nullptr, nullptr, nullptr, nullptr, 0);
        grid_bar(&epoch);
        // P3: scan (+dt-proj, +gate)
        scan_phase(dsm, cta, L_alog, L_skip, L_dpw, L_dpb);
        grid_bar(&epoch);
        // P4: h += gate @ opw^T
        if (cta < 4)
            gemm_tile(dsm, g_gate, DI, L_opw, DI, nullptr, g_h, DMODEL,
                      LSEQ, DMODEL, DI, 0, 1, nullptr, nullptr, 0,
                      nullptr, nullptr, nullptr, nullptr, cta*TBN);
        grid_bar(&epoch);
        // P5: v = LN2(h) @ Wv^T + bv
        if (cta < 4)
            gemm_tile(dsm, g_h, DMODEL, L_aivw, DMODEL, L_aivb, g_v, DMODEL,
                      LSEQ, DMODEL, DMODEL, 0, 0, L_n2w, L_n2b, 1,
                      nullptr, nullptr, nullptr, nullptr, cta*TBN);
        grid_bar(&epoch);
        // P6: h += v @ aow^T + aob
        if (cta < 4)
            gemm_tile(dsm, g_v, DMODEL, L_aow, DMODEL, L_aob, g_h, DMODEL,
                      LSEQ, DMODEL, DMODEL, 0, 1, nullptr, nullptr, 0,
                      nullptr, nullptr, nullptr, nullptr, cta*TBN);
        grid_bar(&epoch);
    }

    // final LN: CTA handles 8 rows, one warp per row
    {
        int w = tid >> 5, lane = tid & 31;
        int l = cta*8 + w;
        float s = 0.f, s2 = 0.f;
        for (int k = lane; k < DMODEL; k += 32) {
            float v = g_h[l*DMODEL + k];
            s += v; s2 += v*v;
        }
        #pragma unroll
        for (int o = 16; o > 0; o >>= 1) {
            s  += __shfl_xor_sync(0xffffffffu, s, o);
            s2 += __shfl_xor_sync(0xffffffffu, s2, o);
        }
        float mean = s * (1.f/DMODEL);
        float rstd = rsqrtf(s2 * (1.f/DMODEL) - mean*mean + 1e-5f);
        for (int k = lane; k < DMODEL; k += 32)
            g_hf[l*DMODEL + k] = (g_h[l*DMODEL + k] - mean)*rstd*nfw[k] + nfb[k];
    }
}

// ---------------- head GEMM (standalone, grid 500) ----------------
__global__ void __launch_bounds__(256)
k_head(const float* __restrict__ A, const float* __restrict__ W,
       const float* __restrict__ bias, float* __restrict__ C) {
    constexpr int BM = 128;
    constexpr int AW = 2*BM*SW;
    constexpr int WW = 2*TBN*SW;
    __shared__ __align__(16) uint32_t sm[2*AW + 2*WW];
    uint32_t* Ash = sm;
    uint32_t* Asl = sm + AW;
    uint32_t* Wsh = sm + 2*AW;
    uint32_t* Wsl = sm + 2*AW + WW;
    int tid = threadIdx.x;
    int wid = tid >> 5, lane = tid & 31;
    int wm = wid >> 1, wn = wid & 1;
    int g = lane >> 2, t = lane & 3;
    int n0 = blockIdx.x * TBN;
    const int K = DMODEL, N = VOCAB, ldc = VOCAB;

    float acc[2][4][4] = {};
    float4 rA[2], rW;
    auto load_tile = [&](int k0) {
        #pragma unroll
        for (int i = 0; i < 2; i++) {
            int slot = tid + i*256;
            int m = slot >> 2, gk = k0 + (slot & 3)*4;
            rA[i] = *reinterpret_cast<const float4*>(&A[(size_t)m*K + gk]);
        }
        int gn = n0 + (tid >> 2), gk = k0 + (tid & 3)*4;
        rW = *reinterpret_cast<const float4*>(&W[(size_t)gn*K + gk]);
    };
    auto store_tile = [&](int s) {
        #pragma unroll
        for (int i = 0; i < 2; i++) {
            int slot = tid + i*256;
            int m = slot >> 2, kw = (slot & 3)*2;
            float4 v = rA[i];
            uint32_t h0 = packbf(v.x, v.y), h1 = packbf(v.z, v.w);
            __nv_bfloat162 b0 = *reinterpret_cast<__nv_bfloat162*>(&h0);
            __nv_bfloat162 b1 = *reinterpret_cast<__nv_bfloat162*>(&h1);
            Ash[(s*BM+m)*SW+kw]   = h0; Ash[(s*BM+m)*SW+kw+1] = h1;
            Asl[(s*BM+m)*SW+kw]   = packbf(v.x - __low2float(b0), v.y - __high2float(b0));
            Asl[(s*BM+m)*SW+kw+1] = packbf(v.z - __low2float(b1), v.w - __high2float(b1));
        }
        int n = tid >> 2, kw = (tid & 3)*2;
        float4 v = rW;
        uint32_t h0 = packbf(v.x, v.y), h1 = packbf(v.z, v.w);
        __nv_bfloat162 b0 = *reinterpret_cast<__nv_bfloat162*>(&h0);
        __nv_bfloat162 b1 = *reinterpret_cast<__nv_bfloat162*>(&h1);
        Wsh[(s*TBN+n)*SW+kw]   = h0; Wsh[(s*TBN+n)*SW+kw+1] = h1;
        Wsl[(s*TBN+n)*SW+kw]   = packbf(v.x - __low2float(b0), v.y - __high2float(b0));
        Wsl[(s*TBN+n)*SW+kw+1] = packbf(v.z - __low2float(b1), v.w - __high2float(b1));
    };

    int nt = K / TBK;
    load_tile(0);
    store_tile(0);
    __syncthreads();
    for (int it = 0; it < nt; it++) {
        int cur = it & 1;
        if (it + 1 < nt) load_tile((it+1) * TBK);
        uint32_t ah[2][4], al[2][4], bh[4][2], bl[4][2];
        #pragma unroll
        for (int mf = 0; mf < 2; mf++) {
            int mr = wm*32 + mf*16;
            ah[mf][0] = Ash[(cur*BM+mr+g  )*SW+t  ];
            ah[mf][1] = Ash[(cur*BM+mr+8+g)*SW+t  ];
            ah[mf][2] = Ash[(cur*BM+mr+g  )*SW+t+4];
            ah[mf][3] = Ash[(cur*BM+mr+8+g)*SW+t+4];
            al[mf][0] = Asl[(cur*BM+mr+g  )*SW+t  ];
            al[mf][1] = Asl[(cur*BM+mr+8+g)*SW+t  ];
            al[mf][2] = Asl[(cur*BM+mr+g  )*SW+t+4];
            al[mf][3] = Asl[(cur*BM+mr+8+g)*SW+t+4];
        }
        #pragma unroll
        for (int nf = 0; nf < 4; nf++) {
            int nr = wn*32 + nf*8;
            bh[nf][0] = Wsh[(cur*TBN+nr+g)*SW+t  ];
            bh[nf][1] = Wsh[(cur*TBN+nr+g)*SW+t+4];
            bl[nf][0] = Wsl[(cur*TBN+nr+g)*SW+t  ];
            bl[nf][1] = Wsl[(cur*TBN+nr+g)*SW+t+4];
        }
        #pragma unroll
        for (int mf = 0; mf < 2; mf++)
            #pragma unroll
            for (int nf = 0; nf < 4; nf++) {
                mma16(acc[mf][nf], al[mf], bh[nf]);
                mma16(acc[mf][nf], ah[mf], bl[nf]);
                mma16(acc[mf][nf], ah[mf], bh[nf]);
            }
        if (it + 1 < nt) store_tile(cur ^ 1);
        __syncthreads();
    }
    #pragma unroll
    for (int mf = 0; mf < 2; mf++)
        #pragma unroll
        for (int nf = 0; nf < 4; nf++)
            #pragma unroll
            for (int e = 0; e < 4; e++) {
                int gm = wm*32 + mf*16 + g + (e >> 1)*8;
                int gn = n0 + wn*32 + nf*8 + 2*t + (e & 1);
                if (gn < N)
                    C[(size_t)gm*ldc + gn] = acc[mf][nf][e] + bias[gn];
            }
}

// ---------------- launch ----------------
extern "C" void kernel_launch(void* const* d_in, const int* in_sizes, int n_in,
                              void* d_out, int out_size) {
    const int*   x     = (const int*)  d_in[0];
    const float* emb   = (const float*)d_in[1];
    const float* n1w   = (const float*)d_in[2];
    const float* n1b   = (const float*)d_in[3];
    const float* n2w   = (const float*)d_in[4];
    const float* n2b   = (const float*)d_in[5];
    const float* ipw   = (const float*)d_in[6];
    const float* cw    = (const float*)d_in[7];
    const float* cb    = (const float*)d_in[8];
    const float* xpw   = (const float*)d_in[9];
    const float* dpw   = (const float*)d_in[10];
    const float* dpb   = (const float*)d_in[11];
    const float* alog  = (const float*)d_in[12];
    const float* dskip = (const float*)d_in[13];
    const float* opw   = (const float*)d_in[14];
    const float* aiw   = (const float*)d_in[15];
    const float* aib   = (const float*)d_in[16];
    const float* aow   = (const float*)d_in[17];
    const float* aob   = (const float*)d_in[18];
    const float* nfw   = (const float*)d_in[19];
    const float* nfb   = (const float*)d_in[20];
    const float* headb = (const float*)d_in[21];
    float* out = (float*)d_out;

    static bool attr_set = false;
    if (!attr_set) {
        cudaFuncSetAttribute(k_mega, cudaFuncAttributeMaxDynamicSharedMemorySize, 61440);
        attr_set = true;
    }

    unsigned* pbar; cudaGetSymbolAddress((void**)&pbar, g_bar);
    float* phf;     cudaGetSymbolAddress((void**)&phf, g_hf);

    cudaMemsetAsync(pbar, 0, 2*sizeof(unsigned));

    k_mega<<<GCTA, TT, 61440>>>(x, emb, n1w, n1b, n2w, n2b, ipw, cw, cb,
                                xpw, dpw, dpb, alog, dskip, opw,
                                aiw, aib, aow, aob, nfw, nfb);

    k_head<<<VOCAB/TBN, 256>>>(phf, emb, headb, out);
}

// round 12
// speedup vs baseline: 1.2281x; 1.2281x over previous
#include <cuda_runtime.h>
#include <cuda_bf16.h>
#include <cstdint>
#include <math.h>

#define VOCAB 32000
#define DMODEL 256
#define NLAYER 6
#define DS 16
#define DC 4
#define DI 512
#define DTR 16
#define LSEQ 128
#define XDW 48             // DTR + 2*DS
#define KSPLIT 4

// All 16 replicas are provably identical (replica-symmetric network); compute one.
// Attention with identical replicas => softmax uniform => branch is affine with
// combined weight Wc = Wo@Wv, bias bc = Wo@bv + ob (precomputed per layer).

// ---------------- scratch (device globals; no allocation allowed) ----------
__device__ float g_h[LSEQ*DMODEL];          // residual ping
__device__ float g_h2[LSEQ*DMODEL];         // residual pong
__device__ float g_z[LSEQ*DI];
__device__ float g_u[LSEQ*DI];
__device__ float g_xdbl[KSPLIT*LSEQ*XDW];
__device__ float g_gate[LSEQ*DI];
__device__ float g_wc[NLAYER*DMODEL*DMODEL]; // combined attn weights
__device__ float g_bc[NLAYER*DMODEL];        // combined attn bias
__device__ float g_hf[LSEQ*DMODEL];          // final LN

// ---------------- helpers ----------
__device__ __forceinline__ float siluf(float x) { return x / (1.f + __expf(-x)); }
__device__ __forceinline__ float softplusf(float x) { return (x > 20.f) ? x : log1pf(__expf(x)); }

__device__ __forceinline__ uint32_t packbf(float x, float y) {
    __nv_bfloat162 h = __floats2bfloat162_rn(x, y);
    return *reinterpret_cast<uint32_t*>(&h);
}

__device__ __forceinline__ void mma16(float* c, const uint32_t* a, const uint32_t* b) {
    asm volatile(
        "mma.sync.aligned.m16n8k16.row.col.f32.bf16.bf16.f32 "
        "{%0,%1,%2,%3}, {%4,%5,%6,%7}, {%8,%9}, {%0,%1,%2,%3};"
        : "+f"(c[0]), "+f"(c[1]), "+f"(c[2]), "+f"(c[3])
        : "r"(a[0]), "r"(a[1]), "r"(a[2]), "r"(a[3]), "r"(b[0]), "r"(b[1]));
}

__device__ float blockReduceSum256(float v) {
    __shared__ float s[8];
    __shared__ float tot;
    int lane = threadIdx.x & 31, wid = threadIdx.x >> 5;
    #pragma unroll
    for (int o = 16; o > 0; o >>= 1) v += __shfl_xor_sync(0xffffffffu, v, o);
    if (lane == 0) s[wid] = v;
    __syncthreads();
    if (wid == 0) {
        float w = (lane < 8) ? s[lane] : 0.f;
        #pragma unroll
        for (int o = 4; o > 0; o >>= 1) w += __shfl_xor_sync(0xffffffffu, w, o);
        if (lane == 0) tot = w;
    }
    __syncthreads();
    float r = tot;
    __syncthreads();
    return r;
}

// ---------------- prep: combine attn weights + biases + embed --------------
// grid (16, 1, 7), block 256.
// z<6: Wc[z] = Wo[z] @ Wv[z]  (16 CTAs of 64x64 tiles)
// z==6: bx<6 -> bc[bx];  bx>=6 -> embed (10 CTAs)
__global__ void k_prep(const int* __restrict__ x, const float* __restrict__ emb,
                       const float* __restrict__ aiw, const float* __restrict__ aib,
                       const float* __restrict__ aow, const float* __restrict__ aob) {
    int z = blockIdx.z;
    int tid = threadIdx.x;
    if (z < NLAYER) {
        const float* Wo = aow + (size_t)z*DMODEL*DMODEL;
        const float* Wv = aiw + (size_t)z*3*DMODEL*DMODEL + (size_t)2*DMODEL*DMODEL;
        float* Wc = g_wc + (size_t)z*DMODEL*DMODEL;
        __shared__ float sA[16][65];   // [e][d]
        __shared__ float sW[16][64];   // [e][k]
        int bx = blockIdx.x;
        int d0 = (bx >> 2)*64, k0 = (bx & 3)*64;
        int ty = tid >> 4, tx = tid & 15;
        float acc[4][4] = {};
        for (int e0 = 0; e0 < DMODEL; e0 += 16) {
            {
                int d = tid >> 2, e = (tid & 3)*4;
                float4 v = *reinterpret_cast<const float4*>(&Wo[(size_t)(d0+d)*DMODEL + e0 + e]);
                sA[e+0][d] = v.x; sA[e+1][d] = v.y; sA[e+2][d] = v.z; sA[e+3][d] = v.w;
            }
            {
                int e = tid >> 4, k = (tid & 15)*4;
                float4 v = *reinterpret_cast<const float4*>(&Wv[(size_t)(e0+e)*DMODEL + k0 + k]);
                sW[e][k] = v.x; sW[e][k+1] = v.y; sW[e][k+2] = v.z; sW[e][k+3] = v.w;
            }
            __syncthreads();
            #pragma unroll
            for (int e = 0; e < 16; e++) {
                float a[4], w[4];
                #pragma unroll
                for (int i = 0; i < 4; i++) a[i] = sA[e][ty*4+i];
                #pragma unroll
                for (int j = 0; j < 4; j++) w[j] = sW[e][tx*4+j];
                #pragma unroll
                for (int i = 0; i < 4; i++)
                    #pragma unroll
                    for (int j = 0; j < 4; j++) acc[i][j] += a[i]*w[j];
            }
            __syncthreads();
        }
        #pragma unroll
        for (int i = 0; i < 4; i++)
            #pragma unroll
            for (int j = 0; j < 4; j++)
                Wc[(size_t)(d0+ty*4+i)*DMODEL + k0+tx*4+j] = acc[i][j];
    } else {
        int bx = blockIdx.x;
        if (bx < NLAYER) {
            const float* Wo = aow + (size_t)bx*DMODEL*DMODEL;
            const float* bv = aib + (size_t)bx*3*DMODEL + 2*DMODEL;
            const float* ob = aob + (size_t)bx*DMODEL;
            float s = ob[tid];
            for (int e = 0; e < DMODEL; e++) s += Wo[(size_t)tid*DMODEL+e]*bv[e];
            g_bc[bx*DMODEL + tid] = s;
        } else {
            for (int idx = (bx-NLAYER)*256 + tid; idx < LSEQ*DMODEL; idx += 10*256)
                g_h[idx] = emb[(size_t)x[idx >> 8]*DMODEL + (idx & 255)];
        }
    }
}

// final LayerNorm. grid = LSEQ, block = 256.
__global__ void k_ln(const float* __restrict__ in,
                     const float* __restrict__ w, const float* __restrict__ b) {
    int l = blockIdx.x;
    int d = threadIdx.x;
    float v = in[(size_t)l*DMODEL + d];
    float m = blockReduceSum256(v) * (1.f/DMODEL);
    float c = v - m;
    float var = blockReduceSum256(c*c) * (1.f/DMODEL);
    g_hf[(size_t)l*DMODEL + d] = c * rsqrtf(var + 1e-5f) * w[d] + b[d];
}

// ---------------- tensor-core split-bf16 GEMM (near-fp32 accurate) --------
// C[M,N] = act(A[M,K] @ W[N,K]^T + bias)
// mode: 0 = store, 1 = +=, 4 = C = addsrc + result
// mode 3 = in_proj special (BM=128): n0<DI -> fused causal conv+silu -> uout;
//          n0>=DI -> store z half to zout (compact DI-wide).
// lnmode 1 = LayerNorm A rows in prologue (K == LN dim).
// split-K: gridDim.z>1 shifts A,W by z*K cols and C by z*M*ldc.
#define TBN 64
#define TBK 16
#define SW 12
template<int BM>
__global__ void __launch_bounds__(BM*2)
k_gemm_tc(const float* __restrict__ A, int lda,
          const float* __restrict__ W, int ldw,
          const float* __restrict__ bias,
          float* __restrict__ C, int ldc,
          int M, int N, int K, int act, int mode,
          const float* __restrict__ lnw, const float* __restrict__ lnb, int lnmode,
          const float* __restrict__ cvw, const float* __restrict__ cvb,
          float* __restrict__ uout, float* __restrict__ zout,
          const float* __restrict__ addsrc) {
    constexpr int T = BM*2;
    constexpr int AW = 2*BM*SW;
    constexpr int WW = 2*TBN*SW;
    __shared__ __align__(16) uint32_t smem[2*AW + 2*WW];
    __shared__ float sMean[BM], sRstd[BM];
    uint32_t* Ash = smem;
    uint32_t* Asl = smem + AW;
    uint32_t* Wsh = smem + 2*AW;
    uint32_t* Wsl = smem + 2*AW + WW;
    #define ASH(s,m,k) Ash[((s)*BM+(m))*SW+(k)]
    #define ASL(s,m,k) Asl[((s)*BM+(m))*SW+(k)]
    #define WSH(s,n,k) Wsh[((s)*TBN+(n))*SW+(k)]
    #define WSL(s,n,k) Wsl[((s)*TBN+(n))*SW+(k)]

    int tid = threadIdx.x;
    int wid = tid >> 5, lane = tid & 31;
    int wm = wid >> 1, wn = wid & 1;
    int g = lane >> 2, t = lane & 3;
    int m0 = blockIdx.y * BM, n0 = blockIdx.x * TBN;

    if (gridDim.z > 1) {
        A += (size_t)blockIdx.z * K;
        W += (size_t)blockIdx.z * K;
        C += (size_t)blockIdx.z * M * ldc;
    }

    if (lnmode) {
        constexpr int NWARP = T/32;
        for (int r = wid; r < BM; r += NWARP) {
            int gm = m0 + r;
            float s = 0.f, s2 = 0.f;
            for (int k = lane*4; k < K; k += 128) {
                float4 v = *reinterpret_cast<const float4*>(&A[(size_t)gm*lda + k]);
                s  += v.x + v.y + v.z + v.w;
                s2 += v.x*v.x + v.y*v.y + v.z*v.z + v.w*v.w;
            }
            #pragma unroll
            for (int o = 16; o > 0; o >>= 1) {
                s  += __shfl_xor_sync(0xffffffffu, s, o);
                s2 += __shfl_xor_sync(0xffffffffu, s2, o);
            }
            if (lane == 0) {
                float mean = s / K;
                sMean[r] = mean;
                sRstd[r] = rsqrtf(s2 / K - mean*mean + 1e-5f);
            }
        }
        __syncthreads();
    }

    float acc[2][4][4] = {};
    constexpr int NA4 = BM*4/T;
    constexpr int NW4 = TBN*4/T;
    float4 rA[NA4], rW[NW4 ? NW4 : 1];

    auto load_tile = [&](int k0) {
        #pragma unroll
        for (int i = 0; i < NA4; i++) {
            int slot = tid + i*T;
            int m = slot >> 2;
            int gm = m0 + m, gk = k0 + (slot & 3)*4;
            float4 v = make_float4(0.f,0.f,0.f,0.f);
            if (gm < M && gk < K) {
                v = *reinterpret_cast<const float4*>(&A[(size_t)gm*lda + gk]);
                if (lnmode) {
                    float mean = sMean[m], rstd = sRstd[m];
                    float4 w4 = *reinterpret_cast<const float4*>(&lnw[gk]);
                    float4 b4 = *reinterpret_cast<const float4*>(&lnb[gk]);
                    v.x = (v.x - mean)*rstd*w4.x + b4.x;
                    v.y = (v.y - mean)*rstd*w4.y + b4.y;
                    v.z = (v.z - mean)*rstd*w4.z + b4.z;
                    v.w = (v.w - mean)*rstd*w4.w + b4.w;
                }
            }
            rA[i] = v;
        }
        #pragma unroll
        for (int i = 0; i < NW4; i++) {
            int slot = tid + i*T;
            int gn = n0 + (slot >> 2), gk = k0 + (slot & 3)*4;
            float4 v = make_float4(0.f,0.f,0.f,0.f);
            if (gn < N && gk < K)
                v = *reinterpret_cast<const float4*>(&W[(size_t)gn*ldw + gk]);
            rW[i] = v;
        }
    };
    auto store_tile = [&](int s) {
        #pragma unroll
        for (int i = 0; i < NA4; i++) {
            int slot = tid + i*T;
            int m = slot >> 2, kw = (slot & 3)*2;
            float4 v = rA[i];
            uint32_t h0 = packbf(v.x, v.y), h1 = packbf(v.z, v.w);
            __nv_bfloat162 b0 = *reinterpret_cast<__nv_bfloat162*>(&h0);
            __nv_bfloat162 b1 = *reinterpret_cast<__nv_bfloat162*>(&h1);
            ASH(s,m,kw)   = h0; ASH(s,m,kw+1) = h1;
            ASL(s,m,kw)   = packbf(v.x - __low2float(b0), v.y - __high2float(b0));
            ASL(s,m,kw+1) = packbf(v.z - __low2float(b1), v.w - __high2float(b1));
        }
        #pragma unroll
        for (int i = 0; i < NW4; i++) {
            int slot = tid + i*T;
            int n = slot >> 2, kw = (slot & 3)*2;
            float4 v = rW[i];
            uint32_t h0 = packbf(v.x, v.y), h1 = packbf(v.z, v.w);
            __nv_bfloat162 b0 = *reinterpret_cast<__nv_bfloat162*>(&h0);
            __nv_bfloat162 b1 = *reinterpret_cast<__nv_bfloat162*>(&h1);
            WSH(s,n,kw)   = h0; WSH(s,n,kw+1) = h1;
            WSL(s,n,kw)   = packbf(v.x - __low2float(b0), v.y - __high2float(b0));
            WSL(s,n,kw+1) = packbf(v.z - __low2float(b1), v.w - __high2float(b1));
        }
    };

    int nt = (K + TBK - 1) / TBK;
    load_tile(0);
    store_tile(0);
    __syncthreads();

    for (int it = 0; it < nt; it++) {
        int cur = it & 1;
        if (it + 1 < nt) load_tile((it+1) * TBK);
        uint32_t ah[2][4], al[2][4], bh[4][2], bl[4][2];
        #pragma unroll
        for (int mf = 0; mf < 2; mf++) {
            int mr = wm*32 + mf*16;
            ah[mf][0] = ASH(cur, mr + g,     t    );
            ah[mf][1] = ASH(cur, mr + 8 + g, t    );
            ah[mf][2] = ASH(cur, mr + g,     t + 4);
            ah[mf][3] = ASH(cur, mr + 8 + g, t + 4);
            al[mf][0] = ASL(cur, mr + g,     t    );
            al[mf][1] = ASL(cur, mr + 8 + g, t    );
            al[mf][2] = ASL(cur, mr + g,     t + 4);
            al[mf][3] = ASL(cur, mr + 8 + g, t + 4);
        }
        #pragma unroll
        for (int nf = 0; nf < 4; nf++) {
            int nr = wn*32 + nf*8;
            bh[nf][0] = WSH(cur, nr + g, t    );
            bh[nf][1] = WSH(cur, nr + g, t + 4);
            bl[nf][0] = WSL(cur, nr + g, t    );
            bl[nf][1] = WSL(cur, nr + g, t + 4);
        }
        #pragma unroll
        for (int mf = 0; mf < 2; mf++)
            #pragma unroll
            for (int nf = 0; nf < 4; nf++) {
                mma16(acc[mf][nf], al[mf], bh[nf]);
                mma16(acc[mf][nf], ah[mf], bl[nf]);
                mma16(acc[mf][nf], ah[mf], bh[nf]);
            }
        if (it + 1 < nt) store_tile(cur ^ 1);
        __syncthreads();
    }

    if (mode == 3 && n0 < DI) {
        float* cb2 = reinterpret_cast<float*>(smem);   // [128][68]
        #pragma unroll
        for (int mf = 0; mf < 2; mf++)
            #pragma unroll
            for (int nf = 0; nf < 4; nf++)
                #pragma unroll
                for (int e = 0; e < 4; e++) {
                    int r = wm*32 + mf*16 + g + (e >> 1)*8;
                    int c = wn*32 + nf*8 + 2*t + (e & 1);
                    cb2[r*68 + c] = acc[mf][nf][e];
                }
        __syncthreads();
        for (int idx = tid; idx < 128*TBN; idx += T) {
            int tt2 = idx >> 6, c = idx & 63;
            int ch = n0 + c;
            float s = cvb[ch];
            #pragma unroll
            for (int k = 0; k < DC; k++) {
                int tp = tt2 - (DC-1) + k;
                if (tp >= 0) s += cb2[tp*68 + c] * cvw[ch*DC + k];
            }
            uout[(size_t)tt2*DI + ch] = siluf(s);
        }
        return;
    }
    #pragma unroll
    for (int mf = 0; mf < 2; mf++)
        #pragma unroll
        for (int nf = 0; nf < 4; nf++)
            #pragma unroll
            for (int e = 0; e < 4; e++) {
                int gm = m0 + wm*32 + mf*16 + g + (e >> 1)*8;
                int gn = n0 + wn*32 + nf*8 + 2*t + (e & 1);
                if (gm < M && gn < N) {
                    float v = acc[mf][nf][e];
                    if (bias) v += bias[gn];
                    if (act == 1) v = softplusf(v);
                    size_t o = (size_t)gm*ldc + gn;
                    if (mode == 0)      C[o] = v;
                    else if (mode == 1) C[o] += v;
                    else if (mode == 4) C[o] = addsrc[o] + v;
                    else                zout[(size_t)gm*DI + (gn - DI)] = v;
                }
            }
}

// selective scan + fused dt-proj + fused gate.
// grid (DI/32, 1), block 512: tid = s + 16*dl for scan phase.
__global__ void k_scan2(const float* __restrict__ A_log, const float* __restrict__ skipD,
                        const float* __restrict__ dpw, const float* __restrict__ dpb) {
    __shared__ float sdt[LSEQ][32];  // computed dt; recycled as y buffer
    __shared__ float su [LSEQ][32];
    __shared__ float sB [LSEQ][DS];
    __shared__ float sC [LSEQ][DS];
    __shared__ float sX [LSEQ][DTR];
    __shared__ float sW [32][DTR+1];
    int dchunk = blockIdx.x;
    int tid = threadIdx.x;
    const size_t slab = (size_t)LSEQ * XDW;
    for (int idx = tid; idx < LSEQ*32; idx += 512) {
        int tt = idx >> 5, dd = idx & 31;
        su[tt][dd] = g_u[(size_t)tt*DI + dchunk*32 + dd];
    }
    for (int idx = tid; idx < LSEQ*DTR; idx += 512) {
        int tt = idx >> 4, kk = idx & 15;
        size_t base = (size_t)tt*XDW;
        float vx = 0.f, vb = 0.f, vc = 0.f;
        #pragma unroll
        for (int sl = 0; sl < KSPLIT; sl++) {
            vx += g_xdbl[sl*slab + base + kk];
            vb += g_xdbl[sl*slab + base + DTR + kk];
            vc += g_xdbl[sl*slab + base + DTR + DS + kk];
        }
        sX[tt][kk] = vx;
        sB[tt][kk] = vb;
        sC[tt][kk] = vc;
    }
    if (tid < 32*DTR) {
        int dd = tid >> 4, kk = tid & 15;
        sW[dd][kk] = dpw[(dchunk*32 + dd)*DTR + kk];
    }
    __syncthreads();
    for (int idx = tid; idx < LSEQ*32; idx += 512) {
        int tt = idx >> 5, dd = idx & 31;
        float a = dpb[dchunk*32 + dd];
        #pragma unroll
        for (int kk = 0; kk < DTR; kk++) a += sX[tt][kk] * sW[dd][kk];
        sdt[tt][dd] = softplusf(a);
    }
    __syncthreads();
    int s = tid & 15, dl = tid >> 4;
    int d = dchunk*32 + dl;
    float Ads = -__expf(A_log[d*DS + s]);
    float skip = skipD[d];
    float h = 0.f;
    for (int t = 0; t < LSEQ; t++) {
        float dtv = sdt[t][dl], uv = su[t][dl];
        h = __expf(dtv*Ads)*h + dtv*uv*sB[t][s];
        float p = h * sC[t][s];
        p += __shfl_xor_sync(0xffffffffu, p, 8, 16);
        p += __shfl_xor_sync(0xffffffffu, p, 4, 16);
        p += __shfl_xor_sync(0xffffffffu, p, 2, 16);
        p += __shfl_xor_sync(0xffffffffu, p, 1, 16);
        if (s == 0) sdt[t][dl] = p + uv * skip;
    }
    __syncthreads();
    for (int idx = tid; idx < LSEQ*32; idx += 512) {
        int tt = idx >> 5, dd = idx & 31;
        int gd = dchunk*32 + dd;
        float z = g_z[(size_t)tt*DI + gd];
        g_gate[(size_t)tt*DI + gd] = sdt[tt][dd] * siluf(z);
    }
}

// ---------------- launch ----------------
extern "C" void kernel_launch(void* const* d_in, const int* in_sizes, int n_in,
                              void* d_out, int out_size) {
    const int*   x     = (const int*)  d_in[0];
    const float* emb   = (const float*)d_in[1];
    const float* n1w   = (const float*)d_in[2];
    const float* n1b   = (const float*)d_in[3];
    const float* n2w   = (const float*)d_in[4];
    const float* n2b   = (const float*)d_in[5];
    const float* ipw   = (const float*)d_in[6];
    const float* cw    = (const float*)d_in[7];
    const float* cb    = (const float*)d_in[8];
    const float* xpw   = (const float*)d_in[9];
    const float* dpw   = (const float*)d_in[10];
    const float* dpb   = (const float*)d_in[11];
    const float* alog  = (const float*)d_in[12];
    const float* dskip = (const float*)d_in[13];
    const float* opw   = (const float*)d_in[14];
    const float* aiw   = (const float*)d_in[15];
    const float* aib   = (const float*)d_in[16];
    const float* aow   = (const float*)d_in[17];
    const float* aob   = (const float*)d_in[18];
    const float* nfw   = (const float*)d_in[19];
    const float* nfb   = (const float*)d_in[20];
    const float* headb = (const float*)d_in[21];
    float* out = (float*)d_out;

    float* ph;    cudaGetSymbolAddress((void**)&ph, g_h);
    float* ph2;   cudaGetSymbolAddress((void**)&ph2, g_h2);
    float* pz;    cudaGetSymbolAddress((void**)&pz, g_z);
    float* pu;    cudaGetSymbolAddress((void**)&pu, g_u);
    float* pxdbl; cudaGetSymbolAddress((void**)&pxdbl, g_xdbl);
    float* pgate; cudaGetSymbolAddress((void**)&pgate, g_gate);
    float* pwc;   cudaGetSymbolAddress((void**)&pwc, g_wc);
    float* pbc;   cudaGetSymbolAddress((void**)&pbc, g_bc);
    float* phf;   cudaGetSymbolAddress((void**)&phf, g_hf);

    // prep: combined attn weights/biases + embed, one launch
    k_prep<<<dim3(16, 1, 7), 256>>>(x, emb, aiw, aib, aow, aob);

    float* hc = ph;
    float* hn = ph2;

    for (int i = 0; i < NLAYER; i++) {
        const float* L_n1w = n1w + i*DMODEL;
        const float* L_n1b = n1b + i*DMODEL;
        const float* L_n2w = n2w + i*DMODEL;
        const float* L_n2b = n2b + i*DMODEL;
        const float* L_ipw = ipw + (size_t)i*2*DI*DMODEL;
        const float* L_cw  = cw  + (size_t)i*DI*DC;
        const float* L_cb  = cb  + (size_t)i*DI;
        const float* L_xpw = xpw + (size_t)i*XDW*DI;
        const float* L_dpw = dpw + (size_t)i*DI*DTR;
        const float* L_dpb = dpb + (size_t)i*DI;
        const float* L_alog= alog+ (size_t)i*DI*DS;
        const float* L_skip= dskip+(size_t)i*DI;
        const float* L_opw = opw + (size_t)i*DMODEL*DI;
        const float* L_wc  = pwc + (size_t)i*DMODEL*DMODEL;
        const float* L_bc  = pbc + (size_t)i*DMODEL;

        // in_proj (LN1 fused) + conv+silu (u) / z
        k_gemm_tc<128><<<dim3((2*DI)/TBN, 1), 256>>>(
            hc, DMODEL, L_ipw, DMODEL, nullptr, nullptr, 0,
            LSEQ, 2*DI, DMODEL, 0, 3, L_n1w, L_n1b, 1, L_cw, L_cb, pu, pz, nullptr);
        // xdbl partials = u @ xpw^T, split-K x4
        k_gemm_tc<64><<<dim3(1, LSEQ/64, KSPLIT), 128>>>(
            pu, DI, L_xpw, DI, nullptr, pxdbl, XDW,
            LSEQ, XDW, DI/KSPLIT, 0, 0, nullptr, nullptr, 0,
            nullptr, nullptr, nullptr, nullptr, nullptr);
        // scan (+dt-proj, +gate)
        k_scan2<<<dim3(DI/32, 1), 512>>>(L_alog, L_skip, L_dpw, L_dpb);
        // h += gate @ opw^T
        k_gemm_tc<64><<<dim3(DMODEL/TBN, LSEQ/64), 128>>>(
            pgate, DI, L_opw, DI, nullptr, hc, DMODEL,
            LSEQ, DMODEL, DI, 0, 1, nullptr, nullptr, 0,
            nullptr, nullptr, nullptr, nullptr, nullptr);
        // combined attention: hn = hc + LN2(hc) @ Wc^T + bc
        k_gemm_tc<64><<<dim3(DMODEL/TBN, LSEQ/64), 128>>>(
            hc, DMODEL, L_wc, DMODEL, L_bc, hn, DMODEL,
            LSEQ, DMODEL, DMODEL, 0, 4, L_n2w, L_n2b, 1,
            nullptr, nullptr, nullptr, nullptr, hc);
        // swap
        float* tmp = hc; hc = hn; hn = tmp;
    }

    k_ln<<<LSEQ, 256>>>(hc, nfw, nfb);
    k_gemm_tc<128><<<dim3(VOCAB/TBN, 1), 256>>>(
        phf, DMODEL, emb, DMODEL, headb, out, VOCAB,
        LSEQ, VOCAB, DMODEL, 0, 0, nullptr, nullptr, 0,
        nullptr, nullptr, nullptr, nullptr, nullptr);
}